// round 5
// baseline (speedup 1.0000x reference)
#include <cuda_runtime.h>
#include <math.h>
#include <stdint.h>

#define NMAX 100000
#define D 128
#define NG 256

// ---------------- device scratch ----------------
__device__ alignas(16) float g_deg[NMAX];
__device__ alignas(16) float g_dinv[NMAX];
__device__ alignas(16) float g_agg[NMAX * D];
__device__ alignas(16) float g_kv[NMAX * D];
__device__ alignas(16) float g_h[NMAX * 2 * D];
__device__ int   g_start[NG + 1];
__device__ alignas(16) float g_ge[NG * (2 * D + 4)];
__device__ alignas(16) float g_gates[NG * 4];
__device__ alignas(16) float g_cs1[D], g_cq1[D], g_cs2[D], g_cq2[D];
__device__ alignas(16) float g_mu1[D], g_rs1[D], g_mu2[D], g_rs2[D];

__device__ __forceinline__ float to_tf32(float v) {
    uint32_t o;
    asm("cvt.rna.tf32.f32 %0, %1;" : "=r"(o) : "f"(v));
    return __uint_as_float(o);
}

#define MMA_TF32(acc, a0, a1, a2, a3, b0, b1)                                        \
    asm volatile(                                                                     \
        "mma.sync.aligned.m16n8k8.row.col.f32.tf32.tf32.f32 "                         \
        "{%0,%1,%2,%3}, {%4,%5,%6,%7}, {%8,%9}, {%0,%1,%2,%3};"                       \
        : "+f"(acc[0]), "+f"(acc[1]), "+f"(acc[2]), "+f"(acc[3])                      \
        : "r"(__float_as_uint(a0)), "r"(__float_as_uint(a1)),                         \
          "r"(__float_as_uint(a2)), "r"(__float_as_uint(a3)),                         \
          "r"(__float_as_uint(b0)), "r"(__float_as_uint(b1)))

// ---------------- init ----------------
__global__ void k_zero(int n) {
    int i = blockIdx.x * blockDim.x + threadIdx.x;
    if (i < n) g_deg[i] = 0.f;
    if (i < D) { g_cs1[i] = 0.f; g_cq1[i] = 0.f; g_cs2[i] = 0.f; g_cq2[i] = 0.f; }
}

// ---------------- degree count ----------------
__global__ void k_deg(const int* __restrict__ dst, int E) {
    int i = blockIdx.x * blockDim.x + threadIdx.x;
    if (i < E) atomicAdd(&g_deg[dst[i]], 1.f);
}

// ---------------- graph start offsets (batch sorted) ----------------
__global__ void k_gstart(const int* __restrict__ batch, int n) {
    int i = blockIdx.x * blockDim.x + threadIdx.x;
    if (i >= n) return;
    int b  = batch[i];
    int bp = (i == 0) ? -1 : batch[i - 1];
    for (int q = bp + 1; q <= b; ++q) g_start[q] = i;
    if (i == n - 1) {
        for (int q = b + 1; q <= NG; ++q) g_start[q] = n;
    }
}

// ---------------- per-graph stats -> ge [NG, 260] ----------------
__global__ void k_stats(const float* __restrict__ x, int n) {
    __shared__ float sred[128];
    int b = blockIdx.x;
    int j = threadIdx.x;
    int s = g_start[b], e = g_start[b + 1];

    float s0 = 0.f, s1 = 0.f;
    float m0 = -3.4e38f, m1 = -3.4e38f;
    int r = s;
#pragma unroll 4
    for (; r + 2 <= e; r += 2) {
        float v0 = x[(size_t)r * D + j];
        float v1 = x[(size_t)(r + 1) * D + j];
        s0 += v0; m0 = fmaxf(m0, v0);
        s1 += v1; m1 = fmaxf(m1, v1);
    }
    if (r < e) { float v = x[(size_t)r * D + j]; s0 += v; m0 = fmaxf(m0, v); }
    float fsum = s0 + s1;
    float fmax = fmaxf(m0, m1);

    float dsum = 0.f, dmax = -3.4e38f;
    for (int rr = s + j; rr < e; rr += 128) {
        float dv = g_deg[rr];
        dsum += dv; dmax = fmaxf(dmax, dv);
    }
    sred[j] = dsum; __syncthreads();
    for (int off = 64; off; off >>= 1) { if (j < off) sred[j] += sred[j + off]; __syncthreads(); }
    float dsum_t = sred[0]; __syncthreads();
    sred[j] = dmax; __syncthreads();
    for (int off = 64; off; off >>= 1) { if (j < off) sred[j] = fmaxf(sred[j], sred[j + off]); __syncthreads(); }
    float dmax_t = sred[0];

    float cnt0 = (float)(e - s);
    float cntf = fmaxf(cnt0, 1.f);
    float* ge = g_ge + b * (2 * D + 4);
    ge[j]       = fsum / cntf;
    ge[D + j]   = fmax;
    if (j == 0) {
        ge[2 * D + 0] = cntf;
        ge[2 * D + 1] = dsum_t / cntf;
        ge[2 * D + 2] = dmax_t;
        ge[2 * D + 3] = logf(cntf);
    }
}

// ---------------- router MLP + softmax ----------------
__global__ void k_router(const float* __restrict__ rw1, const float* __restrict__ rb1,
                         const float* __restrict__ rw2, const float* __restrict__ rb2,
                         const float* __restrict__ rw3, const float* __restrict__ rb3,
                         const float* __restrict__ temp) {
    __shared__ float sge[260];
    __shared__ float sh1[128];
    __shared__ float sh2[64];
    __shared__ float ssc[4];
    int b = blockIdx.x;
    int j = threadIdx.x;
    for (int k = j; k < 260; k += 128) sge[k] = g_ge[b * 260 + k];
    __syncthreads();
    float a = rb1[j];
#pragma unroll 4
    for (int k = 0; k < 260; ++k) a += sge[k] * rw1[k * 128 + j];
    sh1[j] = fmaxf(a, 0.f);
    __syncthreads();
    if (j < 64) {
        float a2 = rb2[j];
#pragma unroll 4
        for (int k = 0; k < 128; ++k) a2 += sh1[k] * rw2[k * 64 + j];
        sh2[j] = fmaxf(a2, 0.f);
    }
    __syncthreads();
    if (j < 4) {
        float a3 = rb3[j];
#pragma unroll 4
        for (int k = 0; k < 64; ++k) a3 += sh2[k] * rw3[k * 4 + j];
        ssc[j] = a3;
    }
    __syncthreads();
    if (j == 0) {
        float T = temp[0];
        float t0 = ssc[0] / T, t1 = ssc[1] / T, t2 = ssc[2] / T, t3 = ssc[3] / T;
        float m = fmaxf(fmaxf(t0, t1), fmaxf(t2, t3));
        float e0 = expf(t0 - m), e1 = expf(t1 - m), e2 = expf(t2 - m), e3 = expf(t3 - m);
        float inv = 1.f / (e0 + e1 + e2 + e3);
        g_gates[b * 4 + 0] = e0 * inv;
        g_gates[b * 4 + 1] = e1 * inv;
        g_gates[b * 4 + 2] = e2 * inv;
        g_gates[b * 4 + 3] = e3 * inv;
    }
}

// ---------------- self-loop init of agg + dinv ----------------
__global__ void k_selfloop(const float* __restrict__ x, int n) {
    int t = blockIdx.x * blockDim.x + threadIdx.x;
    if (t >= n * 32) return;
    int i = t >> 5;
    int c = (t & 31) * 4;
    float dg = g_deg[i] + 1.f;
    float inv = 1.f / dg;
    float4 xv = *(const float4*)(x + (size_t)i * D + c);
    float4 ov = make_float4(xv.x * inv, xv.y * inv, xv.z * inv, xv.w * inv);
    *(float4*)(g_agg + (size_t)i * D + c) = ov;
    if ((t & 31) == 0) g_dinv[i] = rsqrtf(dg);
}

// ---------------- edge scatter: one warp per 2 edges (ILP), v4 RED ----------------
__global__ void k_edge(const float* __restrict__ x,
                       const int* __restrict__ src,
                       const int* __restrict__ dst, int E) {
    int t = blockIdx.x * blockDim.x + threadIdx.x;
    int w = t >> 5;
    int lane = t & 31;
    int e0 = w * 2;
    if (e0 >= E) return;
    int  s0 = src[e0], d0 = dst[e0];
    float c0 = g_dinv[s0] * g_dinv[d0];
    float4 v0 = *(const float4*)(x + (size_t)s0 * D + lane * 4);
    bool has1 = (e0 + 1) < E;
    int s1 = 0, d1 = 0;
    float c1 = 0.f;
    float4 v1 = make_float4(0.f, 0.f, 0.f, 0.f);
    if (has1) {
        s1 = src[e0 + 1]; d1 = dst[e0 + 1];
        c1 = g_dinv[s1] * g_dinv[d1];
        v1 = *(const float4*)(x + (size_t)s1 * D + lane * 4);
    }
    float* p0 = g_agg + (size_t)d0 * D + lane * 4;
    asm volatile("red.global.add.v4.f32 [%0], {%1,%2,%3,%4};"
                 :: "l"(p0), "f"(v0.x * c0), "f"(v0.y * c0), "f"(v0.z * c0), "f"(v0.w * c0)
                 : "memory");
    if (has1) {
        float* p1 = g_agg + (size_t)d1 * D + lane * 4;
        asm volatile("red.global.add.v4.f32 [%0], {%1,%2,%3,%4};"
                     :: "l"(p1), "f"(v1.x * c1), "f"(v1.y * c1), "f"(v1.z * c1), "f"(v1.w * c1)
                     : "memory");
    }
}

// ---------------- expert combine: tf32 mma + residual + BN1 sums ----------------
// 256 thr = 8 warps: mw 0..3 (rows), nw 0..1 (cols). Tile 64 x 128, K=128.
__global__ __launch_bounds__(256, 1) void k_combine(const float* __restrict__ x,
                                                    const float* __restrict__ ew,
                                                    const float* __restrict__ eb, int n) {
    extern __shared__ float sm[];
    float* Wc  = sm;               // 128*132 = 16896 (tf32, [k][n] padded)
    float* As  = Wc + 16896;       // 64*132  = 8448  (tf32, [m][k] padded)
    float* bc  = As + 8448;        // 128
    float* scs = bc + 128;         // 128
    float* scq = scs + 128;        // 128
    int b = blockIdx.y;
    int s = g_start[b], e = g_start[b + 1];
    int r0 = s + blockIdx.x * 64;
    if (r0 >= e) return;
    int mrows = e - r0; if (mrows > 64) mrows = 64;
    int tid = threadIdx.x;
    int warp = tid >> 5, lane = tid & 31;
    int mw = warp >> 1, nw = warp & 1;
    int gid = lane >> 2, tig = lane & 3;

    float gg0 = g_gates[b * 4 + 0], gg1 = g_gates[b * 4 + 1];
    float gg2 = g_gates[b * 4 + 2], gg3 = g_gates[b * 4 + 3];
    for (int idx = tid; idx < 16384; idx += 256) {
        int d = idx >> 7, o = idx & 127;
        Wc[d * 132 + o] = to_tf32(gg0 * ew[idx] + gg1 * ew[16384 + idx]
                                + gg2 * ew[32768 + idx] + gg3 * ew[49152 + idx]);
    }
    if (tid < 128) {
        bc[tid]  = gg0 * eb[tid] + gg1 * eb[128 + tid] + gg2 * eb[256 + tid] + gg3 * eb[384 + tid];
        scs[tid] = 0.f;
        scq[tid] = 0.f;
    }
    for (int idx = tid; idx < 8192; idx += 256) {
        int m = idx >> 7, d = idx & 127;
        As[m * 132 + d] = to_tf32((m < mrows) ? g_agg[(size_t)(r0 + m) * D + d] : 0.f);
    }
    __syncthreads();

    float acc[8][4];
#pragma unroll
    for (int na = 0; na < 8; ++na)
#pragma unroll
        for (int q = 0; q < 4; ++q) acc[na][q] = 0.f;

#pragma unroll
    for (int ks = 0; ks < 16; ++ks) {
        int kb = ks * 8;
        float a0 = As[(mw * 16 + gid) * 132 + kb + tig];
        float a1 = As[(mw * 16 + gid + 8) * 132 + kb + tig];
        float a2 = As[(mw * 16 + gid) * 132 + kb + tig + 4];
        float a3 = As[(mw * 16 + gid + 8) * 132 + kb + tig + 4];
        const float* wb0 = Wc + (kb + tig) * 132 + nw * 64 + gid;
        const float* wb1 = Wc + (kb + tig + 4) * 132 + nw * 64 + gid;
#pragma unroll
        for (int na = 0; na < 8; ++na) {
            float b0 = wb0[na * 8];
            float b1 = wb1[na * 8];
            MMA_TF32(acc[na], a0, a1, a2, a3, b0, b1);
        }
    }

    int lr0 = mw * 16 + gid;
    int lr1 = lr0 + 8;
    int row0 = r0 + lr0, row1 = r0 + lr1;
#pragma unroll
    for (int na = 0; na < 8; ++na) {
        int col = nw * 64 + na * 8 + 2 * tig;
        float bcx = bc[col], bcy = bc[col + 1];
        float sx = 0.f, sy = 0.f, qx = 0.f, qy = 0.f;
        if (lr0 < mrows) {
            float2 xr = *(const float2*)(x + (size_t)row0 * D + col);
            float vx = acc[na][0] + bcx + xr.x;
            float vy = acc[na][1] + bcy + xr.y;
            *(float2*)(g_kv + (size_t)row0 * D + col) = make_float2(vx, vy);
            sx += vx; sy += vy; qx += vx * vx; qy += vy * vy;
        }
        if (lr1 < mrows) {
            float2 xr = *(const float2*)(x + (size_t)row1 * D + col);
            float vx = acc[na][2] + bcx + xr.x;
            float vy = acc[na][3] + bcy + xr.y;
            *(float2*)(g_kv + (size_t)row1 * D + col) = make_float2(vx, vy);
            sx += vx; sy += vy; qx += vx * vx; qy += vy * vy;
        }
        atomicAdd(&scs[col], sx);
        atomicAdd(&scs[col + 1], sy);
        atomicAdd(&scq[col], qx);
        atomicAdd(&scq[col + 1], qy);
    }
    __syncthreads();
    if (tid < 128) {
        atomicAdd(&g_cs1[tid], scs[tid]);
        atomicAdd(&g_cq1[tid], scq[tid]);
    }
}

// ---------------- BN stat finalize ----------------
__global__ void k_bnstat1(float inv_n) {
    int j = threadIdx.x;
    float m = g_cs1[j] * inv_n;
    g_mu1[j] = m;
    g_rs1[j] = rsqrtf(g_cq1[j] * inv_n - m * m + 1e-5f);
}
__global__ void k_bnstat2(float inv_n) {
    int j = threadIdx.x;
    float m = g_cs2[j] * inv_n;
    g_mu2[j] = m;
    g_rs2[j] = rsqrtf(g_cq2[j] * inv_n - m * m + 1e-5f);
}

// ---------------- FFN GEMM1: tf32 mma (validated R4) ----------------
__global__ __launch_bounds__(512, 1) void k_ffn1(const float* __restrict__ w1,
                                                 const float* __restrict__ fb1,
                                                 const float* __restrict__ bng,
                                                 const float* __restrict__ bnb, int n) {
    extern __shared__ float sm[];
    float* scale = sm;                 // 128
    float* shift = sm + 128;           // 128
    float* As    = sm + 256;           // 128*132
    float* Ws    = As + 16896;         // 32*260
    int tid  = threadIdx.x;
    int warp = tid >> 5, lane = tid & 31;
    int mw = warp >> 1, nw = warp & 1;
    int gid = lane >> 2, tig = lane & 3;
    int r0 = blockIdx.x * 128;

    if (tid < 128) {
        float sc = g_rs1[tid] * bng[tid];
        scale[tid] = sc;
        shift[tid] = bnb[tid] - g_mu1[tid] * sc;
    }
    __syncthreads();
    for (int idx = tid; idx < 16384; idx += 512) {
        int r = idx >> 7, k = idx & 127;
        int row = r0 + r;
        float v = (row < n) ? g_kv[(size_t)row * D + k] * scale[k] + shift[k] : 0.f;
        As[r * 132 + k] = to_tf32(v);
    }

    float acc[16][4];
#pragma unroll
    for (int na = 0; na < 16; ++na)
#pragma unroll
        for (int q = 0; q < 4; ++q) acc[na][q] = 0.f;

    for (int kt = 0; kt < 4; ++kt) {
        __syncthreads();
        for (int idx = tid; idx < 8192; idx += 512) {
            int kk = idx >> 8, nn = idx & 255;
            Ws[kk * 260 + nn] = to_tf32(w1[(kt * 32 + kk) * 256 + nn]);
        }
        __syncthreads();
#pragma unroll
        for (int ks = 0; ks < 4; ++ks) {
            int kb = kt * 32 + ks * 8;
            float a0 = As[(mw * 16 + gid) * 132 + kb + tig];
            float a1 = As[(mw * 16 + gid + 8) * 132 + kb + tig];
            float a2 = As[(mw * 16 + gid) * 132 + kb + tig + 4];
            float a3 = As[(mw * 16 + gid + 8) * 132 + kb + tig + 4];
            const float* wb0 = Ws + (ks * 8 + tig) * 260 + nw * 128 + gid;
            const float* wb1 = Ws + (ks * 8 + tig + 4) * 260 + nw * 128 + gid;
#pragma unroll
            for (int na = 0; na < 16; ++na) {
                float b0 = wb0[na * 8];
                float b1 = wb1[na * 8];
                MMA_TF32(acc[na], a0, a1, a2, a3, b0, b1);
            }
        }
    }

    int row0 = r0 + mw * 16 + gid;
    int row1 = row0 + 8;
#pragma unroll
    for (int na = 0; na < 16; ++na) {
        int col = nw * 128 + na * 8 + 2 * tig;
        float bbx = fb1[col], bby = fb1[col + 1];
        if (row0 < n) {
            float2 v;
            v.x = fmaxf(acc[na][0] + bbx, 0.f);
            v.y = fmaxf(acc[na][1] + bby, 0.f);
            *(float2*)(g_h + (size_t)row0 * 256 + col) = v;
        }
        if (row1 < n) {
            float2 v;
            v.x = fmaxf(acc[na][2] + bbx, 0.f);
            v.y = fmaxf(acc[na][3] + bby, 0.f);
            *(float2*)(g_h + (size_t)row1 * 256 + col) = v;
        }
    }
}

// ---------------- FFN GEMM2: tf32 mma + residual + BN2 sums ----------------
// 512 thr = 16 warps: mw 0..7 (rows), nw 0..1 (cols). Tile 128 x 128, K=256 chunked 32.
__global__ __launch_bounds__(512, 1) void k_ffn2(const float* __restrict__ w2,
                                                 const float* __restrict__ b2,
                                                 const float* __restrict__ bng,
                                                 const float* __restrict__ bnb, int n) {
    __shared__ float scale[128], shift[128];
    __shared__ float As[128 * 36];     // [m][k-chunk] tf32, pad 36
    __shared__ float Ws[32 * 132];     // [k-chunk][n] tf32, pad 132
    __shared__ float scs[128], scq[128];
    int tid  = threadIdx.x;
    int warp = tid >> 5, lane = tid & 31;
    int mw = warp >> 1, nw = warp & 1;
    int gid = lane >> 2, tig = lane & 3;
    int r0 = blockIdx.x * 128;

    if (tid < 128) {
        float sc = g_rs1[tid] * bng[tid];
        scale[tid] = sc;
        shift[tid] = bnb[tid] - g_mu1[tid] * sc;
        scs[tid] = 0.f;
        scq[tid] = 0.f;
    }

    float acc[8][4];
#pragma unroll
    for (int na = 0; na < 8; ++na)
#pragma unroll
        for (int q = 0; q < 4; ++q) acc[na][q] = 0.f;

    for (int kt = 0; kt < 8; ++kt) {
        __syncthreads();
        for (int idx = tid; idx < 4096; idx += 512) {
            int r = idx >> 5, kk = idx & 31;
            int row = r0 + r;
            As[r * 36 + kk] = to_tf32((row < n) ? g_h[(size_t)row * 256 + kt * 32 + kk] : 0.f);
        }
        for (int idx = tid; idx < 4096; idx += 512) {
            int kk = idx >> 7, nn = idx & 127;
            Ws[kk * 132 + nn] = to_tf32(w2[(kt * 32 + kk) * 128 + nn]);
        }
        __syncthreads();
#pragma unroll
        for (int ks = 0; ks < 4; ++ks) {
            int kb = ks * 8;
            float a0 = As[(mw * 16 + gid) * 36 + kb + tig];
            float a1 = As[(mw * 16 + gid + 8) * 36 + kb + tig];
            float a2 = As[(mw * 16 + gid) * 36 + kb + tig + 4];
            float a3 = As[(mw * 16 + gid + 8) * 36 + kb + tig + 4];
            const float* wb0 = Ws + (kb + tig) * 132 + nw * 64 + gid;
            const float* wb1 = Ws + (kb + tig + 4) * 132 + nw * 64 + gid;
#pragma unroll
            for (int na = 0; na < 8; ++na) {
                float b0 = wb0[na * 8];
                float b1 = wb1[na * 8];
                MMA_TF32(acc[na], a0, a1, a2, a3, b0, b1);
            }
        }
    }

    int row0 = r0 + mw * 16 + gid;
    int row1 = row0 + 8;
#pragma unroll
    for (int na = 0; na < 8; ++na) {
        int col = nw * 64 + na * 8 + 2 * tig;
        float bbx = b2[col], bby = b2[col + 1];
        float scx = scale[col], scy = scale[col + 1];
        float shx = shift[col], shy = shift[col + 1];
        float sx = 0.f, sy = 0.f, qx = 0.f, qy = 0.f;
        if (row0 < n) {
            float2 kr = *(const float2*)(g_kv + (size_t)row0 * D + col);
            float vx = kr.x * scx + shx + acc[na][0] + bbx;
            float vy = kr.y * scy + shy + acc[na][1] + bby;
            *(float2*)(g_kv + (size_t)row0 * D + col) = make_float2(vx, vy);
            sx += vx; sy += vy; qx += vx * vx; qy += vy * vy;
        }
        if (row1 < n) {
            float2 kr = *(const float2*)(g_kv + (size_t)row1 * D + col);
            float vx = kr.x * scx + shx + acc[na][2] + bbx;
            float vy = kr.y * scy + shy + acc[na][3] + bby;
            *(float2*)(g_kv + (size_t)row1 * D + col) = make_float2(vx, vy);
            sx += vx; sy += vy; qx += vx * vx; qy += vy * vy;
        }
        atomicAdd(&scs[col], sx);
        atomicAdd(&scs[col + 1], sy);
        atomicAdd(&scq[col], qx);
        atomicAdd(&scq[col + 1], qy);
    }
    __syncthreads();
    if (tid < 128) {
        atomicAdd(&g_cs2[tid], scs[tid]);
        atomicAdd(&g_cq2[tid], scq[tid]);
    }
}

// ---------------- final BN2 normalize -> out ----------------
__global__ void k_final(const float* __restrict__ g2, const float* __restrict__ b2,
                        float* __restrict__ out, int n) {
    int t = blockIdx.x * blockDim.x + threadIdx.x;
    if (t >= n * 32) return;
    int i = t >> 5;
    int c = (t & 31) * 4;
    float4 v = *(const float4*)(g_kv + (size_t)i * D + c);
    float o[4];
    float vv[4] = { v.x, v.y, v.z, v.w };
#pragma unroll
    for (int k = 0; k < 4; ++k) {
        int col = c + k;
        o[k] = (vv[k] - g_mu2[col]) * g_rs2[col] * g2[col] + b2[col];
    }
    *(float4*)(out + (size_t)i * D + c) = make_float4(o[0], o[1], o[2], o[3]);
}

// ---------------- launch ----------------
extern "C" void kernel_launch(void* const* d_in, const int* in_sizes, int n_in,
                              void* d_out, int out_size) {
    const float* x     = (const float*)d_in[0];
    const int*   ei    = (const int*)d_in[1];
    const int*   batch = (const int*)d_in[2];
    const float* temp = (const float*)d_in[3];
    const float* rw1  = (const float*)d_in[4];
    const float* rb1  = (const float*)d_in[5];
    const float* rw2  = (const float*)d_in[6];
    const float* rb2  = (const float*)d_in[7];
    const float* rw3  = (const float*)d_in[8];
    const float* rb3  = (const float*)d_in[9];
    const float* ew   = (const float*)d_in[10];
    const float* eb   = (const float*)d_in[11];
    const float* bn1g = (const float*)d_in[12];
    const float* bn1b = (const float*)d_in[13];
    const float* fw1  = (const float*)d_in[14];
    const float* fb1  = (const float*)d_in[15];
    const float* fw2  = (const float*)d_in[16];
    const float* fb2  = (const float*)d_in[17];
    const float* bn2g = (const float*)d_in[18];
    const float* bn2b = (const float*)d_in[19];
    float* out = (float*)d_out;

    int n = in_sizes[0] / D;
    int E = in_sizes[1] / 2;

    const int COMB_SMEM = (16896 + 8448 + 128 + 256) * 4;    // 102912
    const int F1_SMEM   = (256 + 16896 + 8320) * 4;          // 101888
    cudaFuncSetAttribute(k_combine, cudaFuncAttributeMaxDynamicSharedMemorySize, COMB_SMEM);
    cudaFuncSetAttribute(k_ffn1,    cudaFuncAttributeMaxDynamicSharedMemorySize, F1_SMEM);

    // k_edge kept in the 4th launch slot (the ncu-profiled one).
    k_zero<<<(n + 255) / 256, 256>>>(n);
    k_deg<<<(E + 255) / 256, 256>>>(ei + E, E);
    k_selfloop<<<(n * 32 + 255) / 256, 256>>>(x, n);
    {
        int warps = (E + 1) / 2;
        long long tot = (long long)warps * 32;
        int blocks = (int)((tot + 255) / 256);
        k_edge<<<blocks, 256>>>(x, ei, ei + E, E);
    }
    k_gstart<<<(n + 255) / 256, 256>>>(batch, n);
    k_stats<<<NG, 128>>>(x, n);
    k_router<<<NG, 128>>>(rw1, rb1, rw2, rb2, rw3, rb3, temp);
    k_combine<<<dim3(32, NG), 256, COMB_SMEM>>>(x, ew, eb, n);
    k_bnstat1<<<1, 128>>>(1.f / (float)n);
    k_ffn1<<<(n + 127) / 128, 512, F1_SMEM>>>(fw1, fb1, bn1g, bn1b, n);
    k_ffn2<<<(n + 127) / 128, 512>>>(fw2, fb2, bn1g, bn1b, n);
    k_bnstat2<<<1, 128>>>(1.f / (float)n);
    k_final<<<(n * 32 + 255) / 256, 256>>>(bn2g, bn2b, out, n);
}

// round 7
// speedup vs baseline: 1.0863x; 1.0863x over previous
#include <cuda_runtime.h>
#include <math.h>
#include <stdint.h>

#define NMAX 100000
#define D 128
#define NG 256

// ---------------- device scratch ----------------
__device__ alignas(16) float g_deg[NMAX];
__device__ alignas(16) float g_dinv[NMAX];
__device__ alignas(16) float g_agg[NMAX * D];
__device__ alignas(16) float g_kv[NMAX * D];
__device__ alignas(16) float g_h[NMAX * 2 * D];
__device__ int   g_start[NG + 1];
__device__ alignas(16) float g_ge[NG * (2 * D + 4)];
__device__ alignas(16) float g_gates[NG * 4];
__device__ alignas(16) float g_cs1[D], g_cq1[D], g_cs2[D], g_cq2[D];
__device__ alignas(16) float g_mu1[D], g_rs1[D], g_mu2[D], g_rs2[D];

__device__ __forceinline__ float to_tf32(float v) {
    uint32_t o;
    asm("cvt.rna.tf32.f32 %0, %1;" : "=r"(o) : "f"(v));
    return __uint_as_float(o);
}

// ---------------- init ----------------
__global__ void k_zero(int n) {
    int i = blockIdx.x * blockDim.x + threadIdx.x;
    if (i < n) g_deg[i] = 0.f;
    if (i < D) { g_cs1[i] = 0.f; g_cq1[i] = 0.f; g_cs2[i] = 0.f; g_cq2[i] = 0.f; }
}

// ---------------- degree count ----------------
__global__ void k_deg(const int* __restrict__ dst, int E) {
    int i = blockIdx.x * blockDim.x + threadIdx.x;
    if (i < E) atomicAdd(&g_deg[dst[i]], 1.f);
}

// ---------------- graph start offsets (batch sorted) ----------------
__global__ void k_gstart(const int* __restrict__ batch, int n) {
    int i = blockIdx.x * blockDim.x + threadIdx.x;
    if (i >= n) return;
    int b  = batch[i];
    int bp = (i == 0) ? -1 : batch[i - 1];
    for (int q = bp + 1; q <= b; ++q) g_start[q] = i;
    if (i == n - 1) {
        for (int q = b + 1; q <= NG; ++q) g_start[q] = n;
    }
}

// ---------------- per-graph stats -> ge [NG, 260] ----------------
__global__ void k_stats(const float* __restrict__ x, int n) {
    __shared__ float sred[128];
    int b = blockIdx.x;
    int j = threadIdx.x;
    int s = g_start[b], e = g_start[b + 1];

    float s0 = 0.f, s1 = 0.f;
    float m0 = -3.4e38f, m1 = -3.4e38f;
    int r = s;
#pragma unroll 4
    for (; r + 2 <= e; r += 2) {
        float v0 = x[(size_t)r * D + j];
        float v1 = x[(size_t)(r + 1) * D + j];
        s0 += v0; m0 = fmaxf(m0, v0);
        s1 += v1; m1 = fmaxf(m1, v1);
    }
    if (r < e) { float v = x[(size_t)r * D + j]; s0 += v; m0 = fmaxf(m0, v); }
    float fsum = s0 + s1;
    float fmax = fmaxf(m0, m1);

    float dsum = 0.f, dmax = -3.4e38f;
    for (int rr = s + j; rr < e; rr += 128) {
        float dv = g_deg[rr];
        dsum += dv; dmax = fmaxf(dmax, dv);
    }
    sred[j] = dsum; __syncthreads();
    for (int off = 64; off; off >>= 1) { if (j < off) sred[j] += sred[j + off]; __syncthreads(); }
    float dsum_t = sred[0]; __syncthreads();
    sred[j] = dmax; __syncthreads();
    for (int off = 64; off; off >>= 1) { if (j < off) sred[j] = fmaxf(sred[j], sred[j + off]); __syncthreads(); }
    float dmax_t = sred[0];

    float cnt0 = (float)(e - s);
    float cntf = fmaxf(cnt0, 1.f);
    float* ge = g_ge + b * (2 * D + 4);
    ge[j]       = fsum / cntf;
    ge[D + j]   = fmax;
    if (j == 0) {
        ge[2 * D + 0] = cntf;
        ge[2 * D + 1] = dsum_t / cntf;
        ge[2 * D + 2] = dmax_t;
        ge[2 * D + 3] = logf(cntf);
    }
}

// ---------------- router MLP + softmax ----------------
__global__ void k_router(const float* __restrict__ rw1, const float* __restrict__ rb1,
                         const float* __restrict__ rw2, const float* __restrict__ rb2,
                         const float* __restrict__ rw3, const float* __restrict__ rb3,
                         const float* __restrict__ temp) {
    __shared__ float sge[260];
    __shared__ float sh1[128];
    __shared__ float sh2[64];
    __shared__ float ssc[4];
    int b = blockIdx.x;
    int j = threadIdx.x;
    for (int k = j; k < 260; k += 128) sge[k] = g_ge[b * 260 + k];
    __syncthreads();
    float a = rb1[j];
#pragma unroll 4
    for (int k = 0; k < 260; ++k) a += sge[k] * rw1[k * 128 + j];
    sh1[j] = fmaxf(a, 0.f);
    __syncthreads();
    if (j < 64) {
        float a2 = rb2[j];
#pragma unroll 4
        for (int k = 0; k < 128; ++k) a2 += sh1[k] * rw2[k * 64 + j];
        sh2[j] = fmaxf(a2, 0.f);
    }
    __syncthreads();
    if (j < 4) {
        float a3 = rb3[j];
#pragma unroll 4
        for (int k = 0; k < 64; ++k) a3 += sh2[k] * rw3[k * 4 + j];
        ssc[j] = a3;
    }
    __syncthreads();
    if (j == 0) {
        float T = temp[0];
        float t0 = ssc[0] / T, t1 = ssc[1] / T, t2 = ssc[2] / T, t3 = ssc[3] / T;
        float m = fmaxf(fmaxf(t0, t1), fmaxf(t2, t3));
        float e0 = expf(t0 - m), e1 = expf(t1 - m), e2 = expf(t2 - m), e3 = expf(t3 - m);
        float inv = 1.f / (e0 + e1 + e2 + e3);
        g_gates[b * 4 + 0] = e0 * inv;
        g_gates[b * 4 + 1] = e1 * inv;
        g_gates[b * 4 + 2] = e2 * inv;
        g_gates[b * 4 + 3] = e3 * inv;
    }
}

// ---------------- self-loop init of agg + dinv ----------------
__global__ void k_selfloop(const float* __restrict__ x, int n) {
    int t = blockIdx.x * blockDim.x + threadIdx.x;
    if (t >= n * 32) return;
    int i = t >> 5;
    int c = (t & 31) * 4;
    float dg = g_deg[i] + 1.f;
    float inv = 1.f / dg;
    float4 xv = *(const float4*)(x + (size_t)i * D + c);
    float4 ov = make_float4(xv.x * inv, xv.y * inv, xv.z * inv, xv.w * inv);
    *(float4*)(g_agg + (size_t)i * D + c) = ov;
    if ((t & 31) == 0) g_dinv[i] = rsqrtf(dg);
}

// ---------------- edge scatter: one warp per 2 edges (ILP), v4 RED ----------------
__global__ void k_edge(const float* __restrict__ x,
                       const int* __restrict__ src,
                       const int* __restrict__ dst, int E) {
    int t = blockIdx.x * blockDim.x + threadIdx.x;
    int w = t >> 5;
    int lane = t & 31;
    int e0 = w * 2;
    if (e0 >= E) return;
    int  s0 = src[e0], d0 = dst[e0];
    float c0 = g_dinv[s0] * g_dinv[d0];
    float4 v0 = *(const float4*)(x + (size_t)s0 * D + lane * 4);
    bool has1 = (e0 + 1) < E;
    int s1 = 0, d1 = 0;
    float c1 = 0.f;
    float4 v1 = make_float4(0.f, 0.f, 0.f, 0.f);
    if (has1) {
        s1 = src[e0 + 1]; d1 = dst[e0 + 1];
        c1 = g_dinv[s1] * g_dinv[d1];
        v1 = *(const float4*)(x + (size_t)s1 * D + lane * 4);
    }
    float* p0 = g_agg + (size_t)d0 * D + lane * 4;
    asm volatile("red.global.add.v4.f32 [%0], {%1,%2,%3,%4};"
                 :: "l"(p0), "f"(v0.x * c0), "f"(v0.y * c0), "f"(v0.z * c0), "f"(v0.w * c0)
                 : "memory");
    if (has1) {
        float* p1 = g_agg + (size_t)d1 * D + lane * 4;
        asm volatile("red.global.add.v4.f32 [%0], {%1,%2,%3,%4};"
                     :: "l"(p1), "f"(v1.x * c1), "f"(v1.y * c1), "f"(v1.z * c1), "f"(v1.w * c1)
                     : "memory");
    }
}

// ---------------- expert combine + residual + BN1 sums (R4 FFMA version) ----------------
__global__ __launch_bounds__(256, 1) void k_combine(const float* __restrict__ x,
                                                    const float* __restrict__ ew,
                                                    const float* __restrict__ eb, int n) {
    extern __shared__ float sm[];
    float* Wc  = sm;             // 16384
    float* As  = Wc + 16384;     // 128*68
    float* bc  = As + 8704;      // 128
    float* red = bc + 128;       // 2048
    int b = blockIdx.y;
    int s = g_start[b], e = g_start[b + 1];
    int r0 = s + blockIdx.x * 64;
    if (r0 >= e) return;
    int mrows = e - r0; if (mrows > 64) mrows = 64;
    int tid = threadIdx.x;

    float gg0 = g_gates[b * 4 + 0], gg1 = g_gates[b * 4 + 1];
    float gg2 = g_gates[b * 4 + 2], gg3 = g_gates[b * 4 + 3];
    for (int idx = tid; idx < 16384; idx += 256)
        Wc[idx] = gg0 * ew[idx] + gg1 * ew[16384 + idx] + gg2 * ew[32768 + idx] + gg3 * ew[49152 + idx];
    if (tid < 128)
        bc[tid] = gg0 * eb[tid] + gg1 * eb[128 + tid] + gg2 * eb[256 + tid] + gg3 * eb[384 + tid];
    for (int idx = tid; idx < 8192; idx += 256) {
        int m = idx >> 7, d = idx & 127;
        As[d * 68 + m] = (m < mrows) ? g_agg[(size_t)(r0 + m) * D + d] : 0.f;
    }
    __syncthreads();

    int tr = tid >> 4, tc = tid & 15;
    float acc[4][8];
#pragma unroll
    for (int r = 0; r < 4; ++r)
#pragma unroll
        for (int c = 0; c < 8; ++c) acc[r][c] = 0.f;

    for (int d = 0; d < 128; ++d) {
        float4 av = *(const float4*)(As + d * 68 + tr * 4);
        float4 w0 = *(const float4*)(Wc + d * 128 + tc * 8);
        float4 w1 = *(const float4*)(Wc + d * 128 + tc * 8 + 4);
        float a[4] = { av.x, av.y, av.z, av.w };
        float w[8] = { w0.x, w0.y, w0.z, w0.w, w1.x, w1.y, w1.z, w1.w };
#pragma unroll
        for (int r = 0; r < 4; ++r)
#pragma unroll
            for (int c = 0; c < 8; ++c) acc[r][c] += a[r] * w[c];
    }

    float ps[8], pq[8];
#pragma unroll
    for (int c = 0; c < 8; ++c) { ps[c] = 0.f; pq[c] = 0.f; }
#pragma unroll
    for (int r = 0; r < 4; ++r) {
        int lr = tr * 4 + r;
        if (lr < mrows) {
            int row = r0 + lr;
            float4 x0 = *(const float4*)(x + (size_t)row * D + tc * 8);
            float4 x1 = *(const float4*)(x + (size_t)row * D + tc * 8 + 4);
            float xr[8] = { x0.x, x0.y, x0.z, x0.w, x1.x, x1.y, x1.z, x1.w };
            float v[8];
#pragma unroll
            for (int c = 0; c < 8; ++c) {
                v[c] = acc[r][c] + bc[tc * 8 + c] + xr[c];
                ps[c] += v[c];
                pq[c] += v[c] * v[c];
            }
            *(float4*)(g_kv + (size_t)row * D + tc * 8)     = make_float4(v[0], v[1], v[2], v[3]);
            *(float4*)(g_kv + (size_t)row * D + tc * 8 + 4) = make_float4(v[4], v[5], v[6], v[7]);
        }
    }
#pragma unroll
    for (int c = 0; c < 8; ++c) red[tr * 128 + tc * 8 + c] = ps[c];
    __syncthreads();
    if (tid < 128) {
        float t = 0.f;
#pragma unroll
        for (int k = 0; k < 16; ++k) t += red[k * 128 + tid];
        atomicAdd(&g_cs1[tid], t);
    }
    __syncthreads();
#pragma unroll
    for (int c = 0; c < 8; ++c) red[tr * 128 + tc * 8 + c] = pq[c];
    __syncthreads();
    if (tid < 128) {
        float t = 0.f;
#pragma unroll
        for (int k = 0; k < 16; ++k) t += red[k * 128 + tid];
        atomicAdd(&g_cq1[tid], t);
    }
}

// ---------------- BN stat finalize ----------------
__global__ void k_bnstat1(float inv_n) {
    int j = threadIdx.x;
    float m = g_cs1[j] * inv_n;
    g_mu1[j] = m;
    g_rs1[j] = rsqrtf(g_cq1[j] * inv_n - m * m + 1e-5f);
}
__global__ void k_bnstat2(float inv_n) {
    int j = threadIdx.x;
    float m = g_cs2[j] * inv_n;
    g_mu2[j] = m;
    g_rs2[j] = rsqrtf(g_cq2[j] * inv_n - m * m + 1e-5f);
}

// ---------------- FFN GEMM1: tf32 mma (validated R4) ----------------
__global__ __launch_bounds__(512, 1) void k_ffn1(const float* __restrict__ w1,
                                                 const float* __restrict__ fb1,
                                                 const float* __restrict__ bng,
                                                 const float* __restrict__ bnb, int n) {
    extern __shared__ float sm[];
    float* scale = sm;                 // 128
    float* shift = sm + 128;           // 128
    float* As    = sm + 256;           // 128*132
    float* Ws    = As + 16896;         // 32*260
    int tid  = threadIdx.x;
    int warp = tid >> 5, lane = tid & 31;
    int mw = warp >> 1, nw = warp & 1;
    int gid = lane >> 2, tig = lane & 3;
    int r0 = blockIdx.x * 128;

    if (tid < 128) {
        float sc = g_rs1[tid] * bng[tid];
        scale[tid] = sc;
        shift[tid] = bnb[tid] - g_mu1[tid] * sc;
    }
    __syncthreads();
    for (int idx = tid; idx < 16384; idx += 512) {
        int r = idx >> 7, k = idx & 127;
        int row = r0 + r;
        float v = (row < n) ? g_kv[(size_t)row * D + k] * scale[k] + shift[k] : 0.f;
        As[r * 132 + k] = to_tf32(v);
    }

    float acc[16][4];
#pragma unroll
    for (int na = 0; na < 16; ++na)
#pragma unroll
        for (int q = 0; q < 4; ++q) acc[na][q] = 0.f;

    for (int kt = 0; kt < 4; ++kt) {
        __syncthreads();
        for (int idx = tid; idx < 8192; idx += 512) {
            int kk = idx >> 8, nn = idx & 255;
            Ws[kk * 260 + nn] = to_tf32(w1[(kt * 32 + kk) * 256 + nn]);
        }
        __syncthreads();
#pragma unroll
        for (int ks = 0; ks < 4; ++ks) {
            int kb = kt * 32 + ks * 8;
            float a0 = As[(mw * 16 + gid) * 132 + kb + tig];
            float a1 = As[(mw * 16 + gid + 8) * 132 + kb + tig];
            float a2 = As[(mw * 16 + gid) * 132 + kb + tig + 4];
            float a3 = As[(mw * 16 + gid + 8) * 132 + kb + tig + 4];
            const float* wb0 = Ws + (ks * 8 + tig) * 260 + nw * 128 + gid;
            const float* wb1 = Ws + (ks * 8 + tig + 4) * 260 + nw * 128 + gid;
#pragma unroll
            for (int na = 0; na < 16; ++na) {
                float b0 = wb0[na * 8];
                float b1 = wb1[na * 8];
                asm volatile(
                    "mma.sync.aligned.m16n8k8.row.col.f32.tf32.tf32.f32 "
                    "{%0,%1,%2,%3}, {%4,%5,%6,%7}, {%8,%9}, {%0,%1,%2,%3};"
                    : "+f"(acc[na][0]), "+f"(acc[na][1]), "+f"(acc[na][2]), "+f"(acc[na][3])
                    : "r"(__float_as_uint(a0)), "r"(__float_as_uint(a1)),
                      "r"(__float_as_uint(a2)), "r"(__float_as_uint(a3)),
                      "r"(__float_as_uint(b0)), "r"(__float_as_uint(b1)));
            }
        }
    }

    int row0 = r0 + mw * 16 + gid;
    int row1 = row0 + 8;
#pragma unroll
    for (int na = 0; na < 16; ++na) {
        int col = nw * 128 + na * 8 + 2 * tig;
        float bbx = fb1[col], bby = fb1[col + 1];
        if (row0 < n) {
            float2 v;
            v.x = fmaxf(acc[na][0] + bbx, 0.f);
            v.y = fmaxf(acc[na][1] + bby, 0.f);
            *(float2*)(g_h + (size_t)row0 * 256 + col) = v;
        }
        if (row1 < n) {
            float2 v;
            v.x = fmaxf(acc[na][2] + bbx, 0.f);
            v.y = fmaxf(acc[na][3] + bby, 0.f);
            *(float2*)(g_h + (size_t)row1 * 256 + col) = v;
        }
    }
}

// ---------------- FFN GEMM2 + residual + BN2 sums (R4 FFMA version) ----------------
__global__ __launch_bounds__(256, 1) void k_ffn2(const float* __restrict__ w2,
                                                 const float* __restrict__ b2,
                                                 const float* __restrict__ bng,
                                                 const float* __restrict__ bnb, int n) {
    __shared__ float scale[128], shift[128];
    __shared__ __align__(16) float HsT[32 * 132];
    __shared__ __align__(16) float Ws2[32 * 128];
    __shared__ float red[16 * 128];
    int tid = threadIdx.x;
    int r0 = blockIdx.x * 128;
    if (tid < 128) {
        float sc = g_rs1[tid] * bng[tid];
        scale[tid] = sc;
        shift[tid] = bnb[tid] - g_mu1[tid] * sc;
    }
    int tr = tid >> 4, tc = tid & 15;
    float acc[8][8];
#pragma unroll
    for (int r = 0; r < 8; ++r)
#pragma unroll
        for (int c = 0; c < 8; ++c) acc[r][c] = 0.f;

    for (int kt = 0; kt < 8; ++kt) {
        __syncthreads();
        for (int idx = tid; idx < 4096; idx += 256) {
            int r = idx >> 5, kk = idx & 31;
            int row = r0 + r;
            HsT[kk * 132 + r] = (row < n) ? g_h[(size_t)row * 256 + kt * 32 + kk] : 0.f;
        }
        for (int idx = tid; idx < 4096; idx += 256) Ws2[idx] = w2[kt * 4096 + idx];
        __syncthreads();
        for (int dd = 0; dd < 32; ++dd) {
            const float* hp = HsT + dd * 132 + tr * 8;
            float4 a0 = *(const float4*)hp;
            float4 a1 = *(const float4*)(hp + 4);
            const float* wp = Ws2 + dd * 128 + tc * 8;
            float4 w0 = *(const float4*)wp;
            float4 w1v = *(const float4*)(wp + 4);
            float a[8] = { a0.x, a0.y, a0.z, a0.w, a1.x, a1.y, a1.z, a1.w };
            float w[8] = { w0.x, w0.y, w0.z, w0.w, w1v.x, w1v.y, w1v.z, w1v.w };
#pragma unroll
            for (int r = 0; r < 8; ++r)
#pragma unroll
                for (int c = 0; c < 8; ++c) acc[r][c] += a[r] * w[c];
        }
    }
    float ps[8], pq[8];
#pragma unroll
    for (int c = 0; c < 8; ++c) { ps[c] = 0.f; pq[c] = 0.f; }
    float bb[8];
#pragma unroll
    for (int c = 0; c < 8; ++c) bb[c] = b2[tc * 8 + c];
#pragma unroll
    for (int r = 0; r < 8; ++r) {
        int row = r0 + tr * 8 + r;
        if (row < n) {
            float4 k0 = *(const float4*)(g_kv + (size_t)row * D + tc * 8);
            float4 k1 = *(const float4*)(g_kv + (size_t)row * D + tc * 8 + 4);
            float kr[8] = { k0.x, k0.y, k0.z, k0.w, k1.x, k1.y, k1.z, k1.w };
            float v[8];
#pragma unroll
            for (int c = 0; c < 8; ++c) {
                int col = tc * 8 + c;
                float kv1 = kr[c] * scale[col] + shift[col];
                v[c] = kv1 + acc[r][c] + bb[c];
                ps[c] += v[c];
                pq[c] += v[c] * v[c];
            }
            *(float4*)(g_kv + (size_t)row * D + tc * 8)     = make_float4(v[0], v[1], v[2], v[3]);
            *(float4*)(g_kv + (size_t)row * D + tc * 8 + 4) = make_float4(v[4], v[5], v[6], v[7]);
        }
    }
#pragma unroll
    for (int c = 0; c < 8; ++c) red[tr * 128 + tc * 8 + c] = ps[c];
    __syncthreads();
    if (tid < 128) {
        float t = 0.f;
#pragma unroll
        for (int k = 0; k < 16; ++k) t += red[k * 128 + tid];
        atomicAdd(&g_cs2[tid], t);
    }
    __syncthreads();
#pragma unroll
    for (int c = 0; c < 8; ++c) red[tr * 128 + tc * 8 + c] = pq[c];
    __syncthreads();
    if (tid < 128) {
        float t = 0.f;
#pragma unroll
        for (int k = 0; k < 16; ++k) t += red[k * 128 + tid];
        atomicAdd(&g_cq2[tid], t);
    }
}

// ---------------- final BN2 normalize -> out ----------------
__global__ void k_final(const float* __restrict__ g2, const float* __restrict__ b2,
                        float* __restrict__ out, int n) {
    int t = blockIdx.x * blockDim.x + threadIdx.x;
    if (t >= n * 32) return;
    int i = t >> 5;
    int c = (t & 31) * 4;
    float4 v = *(const float4*)(g_kv + (size_t)i * D + c);
    float o[4];
    float vv[4] = { v.x, v.y, v.z, v.w };
#pragma unroll
    for (int k = 0; k < 4; ++k) {
        int col = c + k;
        o[k] = (vv[k] - g_mu2[col]) * g_rs2[col] * g2[col] + b2[col];
    }
    *(float4*)(out + (size_t)i * D + c) = make_float4(o[0], o[1], o[2], o[3]);
}

// ---------------- launch ----------------
extern "C" void kernel_launch(void* const* d_in, const int* in_sizes, int n_in,
                              void* d_out, int out_size) {
    const float* x     = (const float*)d_in[0];
    const int*   ei    = (const int*)d_in[1];
    const int*   batch = (const int*)d_in[2];
    const float* temp = (const float*)d_in[3];
    const float* rw1  = (const float*)d_in[4];
    const float* rb1  = (const float*)d_in[5];
    const float* rw2  = (const float*)d_in[6];
    const float* rb2  = (const float*)d_in[7];
    const float* rw3  = (const float*)d_in[8];
    const float* rb3  = (const float*)d_in[9];
    const float* ew   = (const float*)d_in[10];
    const float* eb   = (const float*)d_in[11];
    const float* bn1g = (const float*)d_in[12];
    const float* bn1b = (const float*)d_in[13];
    const float* fw1  = (const float*)d_in[14];
    const float* fb1  = (const float*)d_in[15];
    const float* fw2  = (const float*)d_in[16];
    const float* fb2  = (const float*)d_in[17];
    const float* bn2g = (const float*)d_in[18];
    const float* bn2b = (const float*)d_in[19];
    float* out = (float*)d_out;

    int n = in_sizes[0] / D;
    int E = in_sizes[1] / 2;

    const int COMB_SMEM = (16384 + 8704 + 128 + 2048) * 4;   // 109056
    const int F1_SMEM   = (256 + 16896 + 8320) * 4;          // 101888
    cudaFuncSetAttribute(k_combine, cudaFuncAttributeMaxDynamicSharedMemorySize, COMB_SMEM);
    cudaFuncSetAttribute(k_ffn1,    cudaFuncAttributeMaxDynamicSharedMemorySize, F1_SMEM);

    // k_edge kept in the 4th launch slot (the ncu-profiled one).
    k_zero<<<(n + 255) / 256, 256>>>(n);
    k_deg<<<(E + 255) / 256, 256>>>(ei + E, E);
    k_selfloop<<<(n * 32 + 255) / 256, 256>>>(x, n);
    {
        int warps = (E + 1) / 2;
        long long tot = (long long)warps * 32;
        int blocks = (int)((tot + 255) / 256);
        k_edge<<<blocks, 256>>>(x, ei, ei + E, E);
    }
    k_gstart<<<(n + 255) / 256, 256>>>(batch, n);
    k_stats<<<NG, 128>>>(x, n);
    k_router<<<NG, 128>>>(rw1, rb1, rw2, rb2, rw3, rb3, temp);
    k_combine<<<dim3(32, NG), 256, COMB_SMEM>>>(x, ew, eb, n);
    k_bnstat1<<<1, 128>>>(1.f / (float)n);
    k_ffn1<<<(n + 127) / 128, 512, F1_SMEM>>>(fw1, fb1, bn1g, bn1b, n);
    k_ffn2<<<(n + 127) / 128, 256>>>(fw2, fb2, bn1g, bn1b, n);
    k_bnstat2<<<1, 128>>>(1.f / (float)n);
    k_final<<<(n * 32 + 255) / 256, 256>>>(bn2g, bn2b, out, n);
}